// round 15
// baseline (speedup 1.0000x reference)
#include <cuda_runtime.h>
#include <stdint.h>

// Problem constants (fixed-shape problem)
#define kB      8
#define kH      1024
#define kW      1536
#define kHW     (kH * kW)
#define kN      2048
#define kBorder 16
#define kXEnd   (kW - kBorder)   // 1520
#define kYEnd   (kH - kBorder)   // 1008
#define kCap    1600000          // per-batch fallback candidate capacity
#define kSCap   49152            // per-batch prefiltered capacity
#define kPreF   0x3D800000u      // 0.0625f bits: prefilter bound on neur
#define kFB     4096             // fine buckets = key32 >> 18
#define kMCap   3072             // survivor capacity
#define kWBuf   64               // per-warp small-candidate staging
#define kRank   32               // rank blocks per batch
#define kTiles  768              // 12 x 8 x kB block-tiles (128px x 128rows)
#define kTPB    96               // tiles per batch
#define kGrid   592              // 4 blocks/SM x 148 SMs (all co-resident)

// Scratch (device globals -- zero-initialized; in-kernel resets restore zeros)
__device__ unsigned long long g_cand[(size_t)kB * kCap];    // fallback only
__device__ unsigned long long g_small[(size_t)kB * kSCap];
__device__ unsigned long long g_sorted[kB * kMCap];
__device__ unsigned int       g_fhist[kB * kFB];
__device__ unsigned int       g_bcur[kB * kFB];             // bucket ends
__device__ unsigned int       g_count[kB];                  // fallback only
__device__ unsigned int       g_scount[kB];
__device__ unsigned int       g_F[kB], g_M[kB];
__device__ int                g_flag[kB];
__device__ unsigned int       g_mdone[kB];                  // mask tiles done
__device__ unsigned int       g_ready[kB];                  // prep published
__device__ unsigned int       g_done[kB];                   // rank blocks done

// ---------------------------------------------------------------------------
// Taylor 2x2 refinement + output write (row r)
__device__ __forceinline__ void taylor_write(const float* sb, unsigned long long v,
                                             unsigned r, float* out, int b) {
    unsigned idx = (unsigned)(v & 0x1FFFFFull);
    int y = (int)(idx / kW), x = (int)(idx % kW);
    int yc = min(max(y, 1), kH - 2);
    int xc = min(max(x, 1), kW - 2);
    const float* p = sb + (size_t)yc * kW + xc;
    float s00 = p[0];
    float sp0 = p[kW],      sm0 = p[-kW];
    float s0p = p[1],       s0m = p[-1];
    float spp = p[kW + 1],  spm = p[kW - 1];
    float smp = p[-kW + 1], smm = p[-kW - 1];
    float gy  = 0.5f * (sp0 - sm0);
    float gx  = 0.5f * (s0p - s0m);
    float hyy = sp0 - 2.0f * s00 + sm0;
    float hxx = s0p - 2.0f * s00 + s0m;
    float hxy = 0.25f * (spp - spm - smp + smm);
    float det = hyy * hxx - hxy * hxy;
    bool  sing = fabsf(det) > 1e-12f;
    float sd = sing ? det : 1.0f;
    float iy = -(hxx * gy - hxy * gx) / sd;
    float ix = -(hyy * gx - hxy * gy) / sd;
    if (!sing) { iy = 0.0f; ix = 0.0f; }
    iy = fminf(fmaxf(iy, -0.5f), 0.5f);
    ix = fminf(fmaxf(ix, -0.5f), 0.5f);
    float* o = out + ((size_t)b * kN + r) * 3;
    o[0] = (float)y + 0.5f + iy;
    o[1] = (float)x + 0.5f + ix;
    o[2] = __uint_as_float((unsigned)(v >> 21));
}

// ---------------------------------------------------------------------------
// Per-row NMS emit; neur values arrive in registers (coalesced row load)
__device__ __forceinline__ void nms_row(
    float4 Bc, float v0, float v1, float v2, float v3, float vel, float ver,
    float4 nv, int lane, int gx, int gy, int b,
    unsigned long long* buf, unsigned* s_cnt_w) {
    float vprev = __shfl_up_sync(0xffffffffu, v3, 1);
    if (lane == 0)  vprev = vel;
    float vnext = __shfl_down_sync(0xffffffffu, v0, 1);
    if (lane == 31) vnext = ver;

    bool c0 = (Bc.x >= fmaxf(vprev, fmaxf(v0, v1))) && (gx     < kXEnd);
    bool c1 = (Bc.y >= fmaxf(v0,    fmaxf(v1, v2))) && (gx + 1 < kXEnd);
    bool c2 = (Bc.z >= fmaxf(v1,    fmaxf(v2, v3))) && (gx + 2 < kXEnd);
    bool c3 = (Bc.w >= fmaxf(v2,    fmaxf(v3, vnext))) && (gx + 3 < kXEnd);
    if (c0 | c1 | c2 | c3) {
        const float nvs[4] = {nv.x, nv.y, nv.z, nv.w};
        const bool  cf[4]  = {c0, c1, c2, c3};
        unsigned rowbase = (unsigned)(gy * kW + gx);
#pragma unroll
        for (int j = 0; j < 4; ++j) {
            if (cf[j]) {
                unsigned key32 = __float_as_uint(fmaxf(nvs[j], 0.0f));
                if (key32 < kPreF) {   // only small keys can reach top-kN
                    atomicAdd(&g_fhist[b * kFB + (key32 >> 18)], 1u);
                    unsigned long long key =
                        ((unsigned long long)key32 << 21) | (rowbase + j);
                    unsigned p = atomicAdd(s_cnt_w, 1u);
                    if (p < kWBuf) buf[p] = key;
                    else {
                        unsigned gp = atomicAdd(&g_scount[b], 1u);
                        if (gp < kSCap) g_small[(size_t)b * kSCap + gp] = key;
                    }
                }
            }
        }
    }
}

// ---------------------------------------------------------------------------
// Fused kernel: mask (all blocks, grid-stride tiles) -> prep (blocks 0..7,
// spin on per-batch tile counter) -> rank (blocks 8..263, spin on ready).
// Co-residency of all kGrid blocks is guaranteed (regs<=64 via launch_bounds,
// smem 41KB, 256 thr => 4 blocks/SM), so intra-grid spins cannot deadlock.
__global__ __launch_bounds__(256, 4) void k_fused(const float* __restrict__ in0,
                                                  const float* __restrict__ in1,
                                                  float* __restrict__ out) {
    union Smem {
        struct { unsigned long long buf[8][kWBuf]; unsigned cnt[8]; } m;   // 4KB
        struct { unsigned fb[kFB]; unsigned w8[8]; } p;                    // 16KB
        struct { unsigned long long keys[kMCap]; unsigned fb[kFB];
                 unsigned w8[8]; } f;                                      // 41KB
    };
    __shared__ Smem su;
    __shared__ unsigned sF, sMF, sT;
    __shared__ int sflag;

    const int tid  = threadIdx.x;
    const int w    = tid >> 5;
    const int lane = tid & 31;
    const int bid  = blockIdx.x;

    // input-order detection (warp-local, 128 samples => P(err) ~ 2^-128)
    int neg = (in0[lane] < 0.f) | (in0[32 + lane] < 0.f) |
              (in0[64 + lane] < 0.f) | (in0[96 + lane] < 0.f);
    unsigned swapm = __ballot_sync(0xffffffffu, neg);
    const float* score = swapm ? in0 : in1;
    const float* neur  = swapm ? in1 : in0;

    // ==================== Phase 1: mask tiles (grid-stride) ====================
    for (int t = bid; t < kTiles; t += kGrid) {
        const int b  = t / kTPB;
        const int xy = t % kTPB;
        const int x0 = kBorder + (xy % 12) * 128;
        const int ys = kBorder + (xy / 12) * 128 + w * 16;   // 16 rows per warp
        const int gx = x0 + lane * 4;
        const bool active = (ys < kYEnd);
        const bool ld_ok = active && (gx + 4 <= kW);
        const bool ledge = active && (lane == 0);
        const bool redge = active && (lane == 31) && (x0 + 128 < kW);
        const float* sb = score + (size_t)b * kHW;
        const float* nb = neur  + (size_t)b * kHW;

        if (lane == 0) su.m.cnt[w] = 0;
        __syncwarp();

        if (active) {
            const float4 z4 = make_float4(0.f, 0.f, 0.f, 0.f);
            float4 A  = ld_ok ? *(const float4*)(sb + (size_t)(ys - 1) * kW + gx) : z4;
            float4 Bv = ld_ok ? *(const float4*)(sb + (size_t)ys * kW + gx)       : z4;
            float la = 0.f, lb = 0.f, ra = 0.f, rb = 0.f;
            if (ledge) { la = sb[(size_t)(ys - 1) * kW + x0 - 1];
                         lb = sb[(size_t)ys * kW + x0 - 1]; }
            if (redge) { ra = sb[(size_t)(ys - 1) * kW + x0 + 128];
                         rb = sb[(size_t)ys * kW + x0 + 128]; }

#pragma unroll
            for (int i = 0; i < 16; i += 2) {
                const int gy = ys + i;
                float4 C  = ld_ok ? *(const float4*)(sb + (size_t)(gy + 1) * kW + gx) : z4;
                float4 D  = ld_ok ? *(const float4*)(sb + (size_t)(gy + 2) * kW + gx) : z4;
                float4 n0 = ld_ok ? *(const float4*)(nb + (size_t)gy * kW + gx)       : z4;
                float4 n1 = ld_ok ? *(const float4*)(nb + (size_t)(gy + 1) * kW + gx) : z4;
                float lc = 0.f, rc = 0.f, ld = 0.f, rd = 0.f;
                if (ledge) { lc = sb[(size_t)(gy + 1) * kW + x0 - 1];
                             ld = sb[(size_t)(gy + 2) * kW + x0 - 1]; }
                if (redge) { rc = sb[(size_t)(gy + 1) * kW + x0 + 128];
                             rd = sb[(size_t)(gy + 2) * kW + x0 + 128]; }
                {
                    float v0 = fmaxf(fmaxf(A.x, Bv.x), C.x);
                    float v1 = fmaxf(fmaxf(A.y, Bv.y), C.y);
                    float v2 = fmaxf(fmaxf(A.z, Bv.z), C.z);
                    float v3 = fmaxf(fmaxf(A.w, Bv.w), C.w);
                    float vel = fmaxf(fmaxf(la, lb), lc);
                    float ver = fmaxf(fmaxf(ra, rb), rc);
                    nms_row(Bv, v0, v1, v2, v3, vel, ver, n0, lane, gx, gy, b,
                            su.m.buf[w], &su.m.cnt[w]);
                }
                {
                    float v0 = fmaxf(fmaxf(Bv.x, C.x), D.x);
                    float v1 = fmaxf(fmaxf(Bv.y, C.y), D.y);
                    float v2 = fmaxf(fmaxf(Bv.z, C.z), D.z);
                    float v3 = fmaxf(fmaxf(Bv.w, C.w), D.w);
                    float vel = fmaxf(fmaxf(lb, lc), ld);
                    float ver = fmaxf(fmaxf(rb, rc), rd);
                    nms_row(C, v0, v1, v2, v3, vel, ver, n1, lane, gx, gy + 1, b,
                            su.m.buf[w], &su.m.cnt[w]);
                }
                A = C; Bv = D; la = lc; lb = ld; ra = rc; rb = rd;
            }
        }

        // warp flush (contiguous)
        __syncwarp();
        unsigned n = min(su.m.cnt[w], (unsigned)kWBuf);
        unsigned base = 0;
        if (lane == 0 && n) base = atomicAdd(&g_scount[b], n);
        base = __shfl_sync(0xffffffffu, base, 0);
        for (unsigned i = lane; i < n; i += 32) {
            unsigned sp = base + i;
            if (sp < kSCap) g_small[(size_t)b * kSCap + sp] = su.m.buf[w][i];
        }

        // publish tile completion (release)
        __syncthreads();
        if (tid == 0) { __threadfence(); atomicAdd(&g_mdone[b], 1u); }
        __syncthreads();
    }

    // ==================== Phase 2: role specialization ====================
    if (bid < kB) {
        // ---------------- prep for batch b ----------------
        const int b = bid;
        if (tid == 0) {
            while (atomicAdd(&g_mdone[b], 0u) < (unsigned)kTPB) __nanosleep(64);
        }
        __syncthreads();
        __threadfence();   // acquire

        if (tid == 0) { sF = kFB - 1; sMF = 0; sT = 0; }
        __syncthreads();

        // read + zero fine hist; block scan (256 threads x 16 buckets)
        unsigned lh[16], local = 0;
        const int base = tid * 16;
        const int o = b * kFB + base;
#pragma unroll
        for (int j = 0; j < 16; ++j) { lh[j] = g_fhist[o + j]; g_fhist[o + j] = 0; local += lh[j]; }
        unsigned incl = local;
#pragma unroll
        for (int d = 1; d < 32; d <<= 1) {
            unsigned v = __shfl_up_sync(~0u, incl, d);
            if (lane >= d) incl += v;
        }
        if (lane == 31) su.p.w8[w] = incl;
        __syncthreads();
        if (tid == 0) {
            unsigned run = 0;
#pragma unroll
            for (int k = 0; k < 8; ++k) { unsigned t2 = su.p.w8[k]; su.p.w8[k] = run; run += t2; }
            sT = run;
        }
        __syncthreads();
        unsigned texcl = incl - local + su.p.w8[w];
        unsigned iend  = texcl + local;
        if (texcl < (unsigned)kN && iend >= (unsigned)kN) {
            unsigned cum = texcl;
#pragma unroll
            for (int j = 0; j < 16; ++j) {
                cum += lh[j];
                if (cum >= (unsigned)kN) { sF = base + j; sMF = cum; break; }
            }
        }
        {
            unsigned run = texcl;
#pragma unroll
            for (int j = 0; j < 16; ++j) { su.p.fb[base + j] = run; run += lh[j]; }
        }
        __syncthreads();

        const unsigned scnt = g_scount[b];
        if (tid == 0) {
            unsigned M = sMF ? sMF : sT;
            int flag = 0;
            if (scnt < (unsigned)kN || scnt > (unsigned)kSCap) flag = 1;
            else if (M > (unsigned)kMCap) flag = 2;
            sflag = flag;
            g_F[b] = sF; g_M[b] = M; g_flag[b] = flag;
        }
        __syncthreads();

        if (sflag == 0) {
            const unsigned F = sF;
            const unsigned long long* src = g_small + (size_t)b * kSCap;
            for (unsigned i0 = tid * 4u; i0 < scnt; i0 += 1024u) {
                unsigned long long v[4];
#pragma unroll
                for (int j = 0; j < 4; ++j) v[j] = (i0 + j < scnt) ? src[i0 + j] : ~0ull;
#pragma unroll
                for (int j = 0; j < 4; ++j) {
                    if (i0 + j < scnt) {
                        unsigned f = (unsigned)(v[j] >> 39);
                        if (f <= F) {
                            unsigned p2 = atomicAdd(&su.p.fb[f], 1u);
                            g_sorted[b * kMCap + p2] = v[j];
                        }
                    }
                }
            }
            __syncthreads();
#pragma unroll
            for (int j = 0; j < 16; ++j) g_bcur[o + j] = su.p.fb[base + j];
        }
        __syncthreads();
        if (tid == 0) { __threadfence(); atomicExch(&g_ready[b], 1u); }

    } else if (bid < kB + kB * kRank) {
        // ---------------- rank for (batch b, group g) ----------------
        const int r = bid - kB;
        const int b = r >> 5;       // kRank = 32
        const int g = r & 31;
        if (tid == 0) {
            while (atomicAdd(&g_ready[b], 0u) == 0u) __nanosleep(64);
        }
        __syncthreads();
        __threadfence();   // acquire

        const int  flag = g_flag[b];
        const unsigned M = g_M[b];
        const float* sb  = score + (size_t)b * kHW;
        const float* nbp = neur  + (size_t)b * kHW;

        if (flag == 0) {
            const unsigned long long* srt = g_sorted + b * kMCap;
            const unsigned* bc = g_bcur + b * kFB;
            for (unsigned p = g * 256u + tid; p < M; p += kRank * 256u) {
                unsigned long long v = srt[p];
                unsigned f = (unsigned)(v >> 39);
                unsigned start = f ? bc[f - 1] : 0u;
                unsigned end   = bc[f];
                unsigned rr = start;
                for (unsigned q = start; q < end; ++q) rr += (srt[q] < v) ? 1u : 0u;
                if (rr < (unsigned)kN) taylor_write(sb, v, rr, out, b);
            }
        } else if (g == 0) {
            // ============ exact fallback (never expected) ============
            const unsigned long long* src;
            unsigned cnt;
            if (flag == 1) {
                for (unsigned i = tid; i < 1504u * 992u; i += 256u) {
                    int y = kBorder + (int)(i / 1504u);
                    int x = kBorder + (int)(i % 1504u);
                    const float* p = sb + (size_t)y * kW + x;
                    float c = p[0];
                    float mx = fmaxf(fmaxf(fmaxf(p[-kW - 1], p[-kW]), fmaxf(p[-kW + 1], p[-1])),
                                     fmaxf(fmaxf(p[1], p[kW - 1]), fmaxf(p[kW], p[kW + 1])));
                    if (c >= mx) {
                        unsigned key32 = __float_as_uint(fmaxf(nbp[(size_t)y * kW + x], 0.0f));
                        unsigned long long key =
                            ((unsigned long long)key32 << 21) | (unsigned)(y * kW + x);
                        unsigned gp = atomicAdd(&g_count[b], 1u);
                        if (gp < kCap) g_cand[(size_t)b * kCap + gp] = key;
                    }
                }
                __syncthreads();
                src = g_cand + (size_t)b * kCap;
                cnt = min(g_count[b], (unsigned)kCap);
            } else {
                src = g_small + (size_t)b * kSCap;
                cnt = min(g_scount[b], (unsigned)kSCap);
            }

            for (int j = tid; j < kFB; j += 256) su.f.fb[j] = 0;
            if (tid == 0) { sF = kFB - 1; sMF = 0; sT = 0; }
            __syncthreads();
            for (unsigned i = tid; i < cnt; i += 256u)
                atomicAdd(&su.f.fb[min((unsigned)(src[i] >> 39), (unsigned)(kFB - 1))], 1u);
            __syncthreads();

            unsigned lh[16], local = 0;
            const int base = tid * 16;
#pragma unroll
            for (int j = 0; j < 16; ++j) { lh[j] = su.f.fb[base + j]; local += lh[j]; }
            unsigned incl = local;
#pragma unroll
            for (int d = 1; d < 32; d <<= 1) {
                unsigned v = __shfl_up_sync(~0u, incl, d);
                if (lane >= d) incl += v;
            }
            if (lane == 31) su.f.w8[w] = incl;
            __syncthreads();
            if (tid == 0) {
                unsigned run = 0;
#pragma unroll
                for (int k = 0; k < 8; ++k) { unsigned t2 = su.f.w8[k]; su.f.w8[k] = run; run += t2; }
                sT = run;
            }
            __syncthreads();
            unsigned texcl = incl - local + su.f.w8[w];
            unsigned iend  = texcl + local;
            if (texcl < (unsigned)kN && iend >= (unsigned)kN) {
                unsigned cum = texcl;
#pragma unroll
                for (int j = 0; j < 16; ++j) {
                    cum += lh[j];
                    if (cum >= (unsigned)kN) { sF = base + j; sMF = cum; break; }
                }
            }
            {
                unsigned run = texcl;
#pragma unroll
                for (int j = 0; j < 16; ++j) { su.f.fb[base + j] = run; run += lh[j]; }
            }
            __syncthreads();
            const unsigned F = sF;
            const unsigned M2 = sMF ? sMF : sT;

            if (M2 <= (unsigned)kMCap) {
                for (unsigned i = tid; i < cnt; i += 256u) {
                    unsigned long long v = src[i];
                    unsigned f = min((unsigned)(v >> 39), (unsigned)(kFB - 1));
                    if (f <= F) {
                        unsigned p2 = atomicAdd(&su.f.fb[f], 1u);
                        su.f.keys[p2] = v;
                    }
                }
                __syncthreads();
                for (unsigned p = tid; p < M2; p += 256u) {
                    unsigned long long v = su.f.keys[p];
                    unsigned f = min((unsigned)(v >> 39), (unsigned)(kFB - 1));
                    unsigned start = f ? su.f.fb[f - 1] : 0u;
                    unsigned end   = su.f.fb[f];
                    unsigned rr = start;
                    for (unsigned q = start; q < end; ++q) rr += (su.f.keys[q] < v) ? 1u : 0u;
                    if (rr < (unsigned)kN) taylor_write(sb, v, rr, out, b);
                }
            } else {
                for (unsigned i = tid; i < cnt; i += 256u) {
                    unsigned long long v = src[i];
                    if (min((unsigned)(v >> 39), (unsigned)(kFB - 1)) > F) continue;
                    unsigned rr = 0;
                    for (unsigned q = 0; q < cnt; ++q) rr += (src[q] < v) ? 1u : 0u;
                    if (rr < (unsigned)kN) taylor_write(sb, v, rr, out, b);
                }
            }
        }

        // done counting; last rank block of batch resets all state
        __syncthreads();
        if (tid == 0) {
            __threadfence();
            unsigned d = atomicAdd(&g_done[b], 1u) + 1u;
            if (d == (unsigned)kRank) {
                atomicExch(&g_mdone[b], 0u);
                atomicExch(&g_ready[b], 0u);
                atomicExch(&g_done[b], 0u);
                atomicExch(&g_scount[b], 0u);
                atomicExch(&g_count[b], 0u);
            }
        }
    }
    // blocks >= kB + kB*kRank: mask-only helpers, exit
}

// ---------------------------------------------------------------------------
extern "C" void kernel_launch(void* const* d_in, const int* in_sizes, int n_in,
                              void* d_out, int out_size) {
    const float* in0 = (const float*)d_in[0];
    const float* in1 = (const float*)d_in[1];
    float* out = (float*)d_out;

    k_fused<<<kGrid, 256>>>(in0, in1, out);
}